// round 1
// baseline (speedup 1.0000x reference)
#include <cuda_runtime.h>
#include <cuda_bf16.h>
#include <mma.h>
#include <math.h>

using namespace nvcuda;

// ---------------- problem constants ----------------
#define DIM   256
#define H1N   128
#define H2N   64
#define TM    128     // rows per CTA in MLP kernel
#define KC    64      // K-chunk for GEMM1
#define NTHREADS 256
#define POOL_ROWS 2048

// ---------------- smem layout (bytes) ----------------
#define OFF_XHI   0        // 128 x 72 bf16  = 18432
#define OFF_XLO   18432
#define OFF_WHI   36864    // up to 128 x 72 bf16 (GEMM2) / 64 x 136 (GEMM1 chunk)
#define OFF_WLO   55296
#define OFF_H1F   73728    // 128 x 132 f32 = 67584   (reused as H2F: 128 x 68 f32)
#define OFF_H2F   73728
#define OFF_H1HI  141312   // 128 x 136 bf16 = 34816
#define OFF_H1LO  176128
#define OFF_BIAS  210944   // 256 floats: [0..127]=b1, [128..191]=b2, [192..255]=w3
#define SMEM_TOTAL 211968

// ---------------- device scratch ----------------
__device__ __nv_bfloat16 g_w1hi[2][DIM * H1N];
__device__ __nv_bfloat16 g_w1lo[2][DIM * H1N];
__device__ __nv_bfloat16 g_w2hi[2][H1N * H2N];
__device__ __nv_bfloat16 g_w2lo[2][H1N * H2N];
__device__ float g_ebuf[600064];
__device__ float g_segsum[4096];

// ---------------- init: zero output + segment sums ----------------
__global__ void init_kernel(float* __restrict__ out, int n) {
    int i = blockIdx.x * blockDim.x + threadIdx.x;
    if (i < n) out[i] = 0.0f;
    if (i < 4096) g_segsum[i] = 0.0f;
}

// ---------------- convert fp32 weights -> bf16 hi/lo ----------------
__global__ void conv_kernel(const float* __restrict__ W1,
                            const float* __restrict__ W2, int set) {
    int i = blockIdx.x * blockDim.x + threadIdx.x;
    if (i < DIM * H1N) {
        float v = W1[i];
        __nv_bfloat16 h = __float2bfloat16(v);
        g_w1hi[set][i] = h;
        g_w1lo[set][i] = __float2bfloat16(v - __bfloat162float(h));
    } else if (i < DIM * H1N + H1N * H2N) {
        int j = i - DIM * H1N;
        float v = W2[j];
        __nv_bfloat16 h = __float2bfloat16(v);
        g_w2hi[set][j] = h;
        g_w2lo[set][j] = __float2bfloat16(v - __bfloat162float(h));
    }
}

// ---------------- fused MLP -> exp(logit) + segment sum ----------------
// CTA: 256 threads (8 warps), 128 rows. Split-bf16 wmma GEMMs (hi/lo, 3 products).
__global__ void __launch_bounds__(NTHREADS, 1)
mlp_kernel(const float* __restrict__ X, const int* __restrict__ idx,
           const float* __restrict__ b1g, const float* __restrict__ b2g,
           const float* __restrict__ w3g, const float* __restrict__ b3g,
           int set, int nRows, int eOff, int sOff) {
    extern __shared__ char smem[];
    __nv_bfloat16* XHI  = (__nv_bfloat16*)(smem + OFF_XHI);
    __nv_bfloat16* XLO  = (__nv_bfloat16*)(smem + OFF_XLO);
    __nv_bfloat16* WHI  = (__nv_bfloat16*)(smem + OFF_WHI);
    __nv_bfloat16* WLO  = (__nv_bfloat16*)(smem + OFF_WLO);
    float*         H1F  = (float*)(smem + OFF_H1F);
    float*         H2F  = (float*)(smem + OFF_H2F);
    __nv_bfloat16* H1HI = (__nv_bfloat16*)(smem + OFF_H1HI);
    __nv_bfloat16* H1LO = (__nv_bfloat16*)(smem + OFF_H1LO);
    float*         BIAS = (float*)(smem + OFF_BIAS);

    const int t = threadIdx.x;
    const int wid = t >> 5;
    const int wm = wid >> 1;     // warp row-tile 0..3  (32 rows each)
    const int wn = wid & 1;      // warp col-tile 0..1  (64 cols in GEMM1, 32 in GEMM2)
    const int rowBase = blockIdx.x * TM;

    // preload biases / w3
    if (t < H1N) BIAS[t] = b1g[t];
    if (t < H2N) { BIAS[128 + t] = b2g[t]; BIAS[192 + t] = w3g[t]; }

    typedef wmma::fragment<wmma::matrix_a, 16, 16, 16, __nv_bfloat16, wmma::row_major> FragA;
    typedef wmma::fragment<wmma::matrix_b, 16, 16, 16, __nv_bfloat16, wmma::row_major> FragB;
    typedef wmma::fragment<wmma::accumulator, 16, 16, 16, float> FragC;

    // ================= GEMM1: [128 x 256] @ [256 x 128] =================
    FragC acc[2][4];
#pragma unroll
    for (int mi = 0; mi < 2; mi++)
#pragma unroll
        for (int ni = 0; ni < 4; ni++) wmma::fill_fragment(acc[mi][ni], 0.0f);

    for (int c = 0; c < DIM / KC; c++) {
        const int k0 = c * KC;
        // load X chunk [128 x 64] -> hi/lo bf16 (stride 72)
#pragma unroll
        for (int i = 0; i < 32; i++) {
            int e = t + i * NTHREADS;
            int r = e >> 6, kk = e & 63;
            float v = 0.0f;
            int gr = rowBase + r;
            if (gr < nRows) v = X[(size_t)gr * DIM + k0 + kk];
            __nv_bfloat16 h = __float2bfloat16(v);
            XHI[r * 72 + kk] = h;
            XLO[r * 72 + kk] = __float2bfloat16(v - __bfloat162float(h));
        }
        // load W1 chunk [64 x 128] (stride 136)
#pragma unroll
        for (int i = 0; i < 32; i++) {
            int e = t + i * NTHREADS;
            int r = e >> 7, col = e & 127;
            WHI[r * 136 + col] = g_w1hi[set][(k0 + r) * H1N + col];
            WLO[r * 136 + col] = g_w1lo[set][(k0 + r) * H1N + col];
        }
        __syncthreads();
#pragma unroll
        for (int ks = 0; ks < KC / 16; ks++) {
            const int kb = ks * 16;
            FragA ahi[2], alo[2];
            FragB bhi[4], blo[4];
#pragma unroll
            for (int mi = 0; mi < 2; mi++) {
                wmma::load_matrix_sync(ahi[mi], XHI + (wm * 32 + mi * 16) * 72 + kb, 72);
                wmma::load_matrix_sync(alo[mi], XLO + (wm * 32 + mi * 16) * 72 + kb, 72);
            }
#pragma unroll
            for (int ni = 0; ni < 4; ni++) {
                wmma::load_matrix_sync(bhi[ni], WHI + kb * 136 + wn * 64 + ni * 16, 136);
                wmma::load_matrix_sync(blo[ni], WLO + kb * 136 + wn * 64 + ni * 16, 136);
            }
#pragma unroll
            for (int mi = 0; mi < 2; mi++)
#pragma unroll
                for (int ni = 0; ni < 4; ni++) {
                    wmma::mma_sync(acc[mi][ni], ahi[mi], bhi[ni], acc[mi][ni]);
                    wmma::mma_sync(acc[mi][ni], ahi[mi], blo[ni], acc[mi][ni]);
                    wmma::mma_sync(acc[mi][ni], alo[mi], bhi[ni], acc[mi][ni]);
                }
        }
        __syncthreads();
    }

    // epilogue 1: bias + relu -> split bf16 (stride 136)
#pragma unroll
    for (int mi = 0; mi < 2; mi++)
#pragma unroll
        for (int ni = 0; ni < 4; ni++)
            wmma::store_matrix_sync(H1F + (wm * 32 + mi * 16) * 132 + wn * 64 + ni * 16,
                                    acc[mi][ni], 132, wmma::mem_row_major);
    __syncthreads();
#pragma unroll
    for (int i = 0; i < 64; i++) {
        int e = t + i * NTHREADS;
        int r = e >> 7, col = e & 127;
        float v = H1F[r * 132 + col] + BIAS[col];
        v = fmaxf(v, 0.0f);
        __nv_bfloat16 h = __float2bfloat16(v);
        H1HI[r * 136 + col] = h;
        H1LO[r * 136 + col] = __float2bfloat16(v - __bfloat162float(h));
    }
    // load full W2 [128 x 64] (stride 72)
#pragma unroll
    for (int i = 0; i < 32; i++) {
        int e = t + i * NTHREADS;
        int r = e >> 6, col = e & 63;
        WHI[r * 72 + col] = g_w2hi[set][r * H2N + col];
        WLO[r * 72 + col] = g_w2lo[set][r * H2N + col];
    }
    __syncthreads();

    // ================= GEMM2: [128 x 128] @ [128 x 64] =================
    FragC acc2[2][2];
#pragma unroll
    for (int mi = 0; mi < 2; mi++)
#pragma unroll
        for (int ni = 0; ni < 2; ni++) wmma::fill_fragment(acc2[mi][ni], 0.0f);
#pragma unroll
    for (int ks = 0; ks < H1N / 16; ks++) {
        const int kb = ks * 16;
        FragA ahi[2], alo[2];
        FragB bhi[2], blo[2];
#pragma unroll
        for (int mi = 0; mi < 2; mi++) {
            wmma::load_matrix_sync(ahi[mi], H1HI + (wm * 32 + mi * 16) * 136 + kb, 136);
            wmma::load_matrix_sync(alo[mi], H1LO + (wm * 32 + mi * 16) * 136 + kb, 136);
        }
#pragma unroll
        for (int ni = 0; ni < 2; ni++) {
            wmma::load_matrix_sync(bhi[ni], WHI + kb * 72 + wn * 32 + ni * 16, 72);
            wmma::load_matrix_sync(blo[ni], WLO + kb * 72 + wn * 32 + ni * 16, 72);
        }
#pragma unroll
        for (int mi = 0; mi < 2; mi++)
#pragma unroll
            for (int ni = 0; ni < 2; ni++) {
                wmma::mma_sync(acc2[mi][ni], ahi[mi], bhi[ni], acc2[mi][ni]);
                wmma::mma_sync(acc2[mi][ni], ahi[mi], blo[ni], acc2[mi][ni]);
                wmma::mma_sync(acc2[mi][ni], alo[mi], bhi[ni], acc2[mi][ni]);
            }
    }
#pragma unroll
    for (int mi = 0; mi < 2; mi++)
#pragma unroll
        for (int ni = 0; ni < 2; ni++)
            wmma::store_matrix_sync(H2F + (wm * 32 + mi * 16) * 68 + wn * 32 + ni * 16,
                                    acc2[mi][ni], 68, wmma::mem_row_major);
    __syncthreads();

    // ================= layer 3 + exp + segment sum =================
    if (t < TM) {
        float s = b3g[0];
#pragma unroll
        for (int j = 0; j < H2N; j++) {
            float v = H2F[t * 68 + j] + BIAS[128 + j];
            v = fmaxf(v, 0.0f);
            s = fmaf(v, BIAS[192 + j], s);
        }
        int gr = rowBase + t;
        if (gr < nRows) {
            float e = expf(s);                // max-subtraction omitted: logits are O(1)
            g_ebuf[eOff + gr] = e;
            atomicAdd(&g_segsum[sOff + idx[gr]], e);
        }
    }
}

// ---------------- pool: att-weighted segment sum (sorted indices) ----------------
__global__ void __launch_bounds__(NTHREADS)
pool_kernel(const float* __restrict__ X, const int* __restrict__ idx,
            int eOff, int sOff, float* __restrict__ out, int nRows) {
    __shared__ float rw[POOL_ROWS];
    __shared__ int   sg[POOL_ROWS];
    const int base = blockIdx.x * POOL_ROWS;
    const int rows = min(POOL_ROWS, nRows - base);

    for (int i = threadIdx.x; i < rows; i += NTHREADS) {
        int g = base + i;
        int s = idx[g];
        sg[i] = s;
        rw[i] = g_ebuf[eOff + g] / g_segsum[sOff + s];
    }
    __syncthreads();

    const int col = threadIdx.x;  // 256 threads = 256 columns
    float acc = 0.0f;
    int cur = sg[0];
    float xv = X[(size_t)base * DIM + col];
    for (int i = 0; i < rows; i++) {
        float xn = 0.0f;
        if (i + 1 < rows) xn = X[(size_t)(base + i + 1) * DIM + col];
        int s = sg[i];
        if (s != cur) {
            atomicAdd(&out[(size_t)cur * DIM + col], acc);
            acc = 0.0f;
            cur = s;
        }
        acc = fmaf(rw[i], xv, acc);
        xv = xn;
    }
    atomicAdd(&out[(size_t)cur * DIM + col], acc);
}

// ---------------- launch ----------------
extern "C" void kernel_launch(void* const* d_in, const int* in_sizes, int n_in,
                              void* d_out, int out_size) {
    const float* emb_nodes = (const float*)d_in[0];
    const float* emb_edges = (const float*)d_in[1];
    const int*   node_index = (const int*)d_in[2];
    const int*   edge_index = (const int*)d_in[3];
    const float* Wn1 = (const float*)d_in[4];
    const float* bn1 = (const float*)d_in[5];
    const float* Wn2 = (const float*)d_in[6];
    const float* bn2 = (const float*)d_in[7];
    const float* Wn3 = (const float*)d_in[8];
    const float* bn3 = (const float*)d_in[9];
    const float* We1 = (const float*)d_in[10];
    const float* be1 = (const float*)d_in[11];
    const float* We2 = (const float*)d_in[12];
    const float* be2 = (const float*)d_in[13];
    const float* We3 = (const float*)d_in[14];
    const float* be3 = (const float*)d_in[15];

    const int n_nodes = in_sizes[0] / DIM;   // 200000
    const int n_edges = in_sizes[1] / DIM;   // 400000
    float* out = (float*)d_out;
    const int num_graphs = 2048;
    const int half = num_graphs * DIM;       // 524288

    init_kernel<<<(out_size + NTHREADS - 1) / NTHREADS, NTHREADS>>>(out, out_size);

    const int convN = DIM * H1N + H1N * H2N;  // 40960
    conv_kernel<<<(convN + NTHREADS - 1) / NTHREADS, NTHREADS>>>(Wn1, Wn2, 0);
    conv_kernel<<<(convN + NTHREADS - 1) / NTHREADS, NTHREADS>>>(We1, We2, 1);

    cudaFuncSetAttribute(mlp_kernel, cudaFuncAttributeMaxDynamicSharedMemorySize, SMEM_TOTAL);

    mlp_kernel<<<(n_nodes + TM - 1) / TM, NTHREADS, SMEM_TOTAL>>>(
        emb_nodes, node_index, bn1, bn2, Wn3, bn3, 0, n_nodes, 0, 0);
    mlp_kernel<<<(n_edges + TM - 1) / TM, NTHREADS, SMEM_TOTAL>>>(
        emb_edges, edge_index, be1, be2, We3, be3, 1, n_edges, 200000, 2048);

    pool_kernel<<<(n_nodes + POOL_ROWS - 1) / POOL_ROWS, NTHREADS>>>(
        emb_nodes, node_index, 0, 0, out, n_nodes);
    pool_kernel<<<(n_edges + POOL_ROWS - 1) / POOL_ROWS, NTHREADS>>>(
        emb_edges, edge_index, 200000, 2048, out + half, n_edges);
}

// round 2
// speedup vs baseline: 1.0007x; 1.0007x over previous
#include <cuda_runtime.h>
#include <cuda_bf16.h>
#include <mma.h>
#include <math.h>

using namespace nvcuda;

// ---------------- problem constants ----------------
#define DIM   256
#define H1N   128
#define H2N   64
#define TM    128     // rows per CTA in MLP kernel
#define KC    64      // K-chunk for GEMM1
#define NTHREADS 256
#define POOL_ROWS 2048

// ---------------- smem layout (bytes) ----------------
#define OFF_XHI   0        // 128 x 72 bf16  = 18432
#define OFF_XLO   18432
#define OFF_WHI   36864    // up to 128 x 72 bf16 (GEMM2) / 64 x 136 (GEMM1 chunk)
#define OFF_WLO   55296
#define OFF_H1F   73728    // 128 x 132 f32 = 67584   (reused as H2F: 128 x 68 f32)
#define OFF_H2F   73728
#define OFF_H1HI  141312   // 128 x 136 bf16 = 34816
#define OFF_H1LO  176128
#define OFF_BIAS  210944   // 256 floats: [0..127]=b1, [128..191]=b2, [192..255]=w3
#define SMEM_TOTAL 211968

// ---------------- device scratch ----------------
__device__ __nv_bfloat16 g_w1hi[2][DIM * H1N];
__device__ __nv_bfloat16 g_w1lo[2][DIM * H1N];
__device__ __nv_bfloat16 g_w2hi[2][H1N * H2N];
__device__ __nv_bfloat16 g_w2lo[2][H1N * H2N];
__device__ float g_ebuf[600064];
__device__ float g_segsum[4096];

// ---------------- init: zero output + segment sums ----------------
__global__ void init_kernel(float* __restrict__ out, int n) {
    int i = blockIdx.x * blockDim.x + threadIdx.x;
    if (i < n) out[i] = 0.0f;
    if (i < 4096) g_segsum[i] = 0.0f;
}

// ---------------- convert fp32 weights -> bf16 hi/lo ----------------
__global__ void conv_kernel(const float* __restrict__ W1,
                            const float* __restrict__ W2, int set) {
    int i = blockIdx.x * blockDim.x + threadIdx.x;
    if (i < DIM * H1N) {
        float v = W1[i];
        __nv_bfloat16 h = __float2bfloat16(v);
        g_w1hi[set][i] = h;
        g_w1lo[set][i] = __float2bfloat16(v - __bfloat162float(h));
    } else if (i < DIM * H1N + H1N * H2N) {
        int j = i - DIM * H1N;
        float v = W2[j];
        __nv_bfloat16 h = __float2bfloat16(v);
        g_w2hi[set][j] = h;
        g_w2lo[set][j] = __float2bfloat16(v - __bfloat162float(h));
    }
}

// ---------------- fused MLP -> exp(logit) + segment sum ----------------
// CTA: 256 threads (8 warps), 128 rows. Split-bf16 wmma GEMMs (hi/lo, 3 products).
__global__ void __launch_bounds__(NTHREADS, 1)
mlp_kernel(const float* __restrict__ X, const int* __restrict__ idx,
           const float* __restrict__ b1g, const float* __restrict__ b2g,
           const float* __restrict__ w3g, const float* __restrict__ b3g,
           int set, int nRows, int eOff, int sOff) {
    extern __shared__ char smem[];
    __nv_bfloat16* XHI  = (__nv_bfloat16*)(smem + OFF_XHI);
    __nv_bfloat16* XLO  = (__nv_bfloat16*)(smem + OFF_XLO);
    __nv_bfloat16* WHI  = (__nv_bfloat16*)(smem + OFF_WHI);
    __nv_bfloat16* WLO  = (__nv_bfloat16*)(smem + OFF_WLO);
    float*         H1F  = (float*)(smem + OFF_H1F);
    float*         H2F  = (float*)(smem + OFF_H2F);
    __nv_bfloat16* H1HI = (__nv_bfloat16*)(smem + OFF_H1HI);
    __nv_bfloat16* H1LO = (__nv_bfloat16*)(smem + OFF_H1LO);
    float*         BIAS = (float*)(smem + OFF_BIAS);

    const int t = threadIdx.x;
    const int wid = t >> 5;
    const int wm = wid >> 1;     // warp row-tile 0..3  (32 rows each)
    const int wn = wid & 1;      // warp col-tile 0..1  (64 cols in GEMM1, 32 in GEMM2)
    const int rowBase = blockIdx.x * TM;

    // preload biases / w3
    if (t < H1N) BIAS[t] = b1g[t];
    if (t < H2N) { BIAS[128 + t] = b2g[t]; BIAS[192 + t] = w3g[t]; }

    typedef wmma::fragment<wmma::matrix_a, 16, 16, 16, __nv_bfloat16, wmma::row_major> FragA;
    typedef wmma::fragment<wmma::matrix_b, 16, 16, 16, __nv_bfloat16, wmma::row_major> FragB;
    typedef wmma::fragment<wmma::accumulator, 16, 16, 16, float> FragC;

    // ================= GEMM1: [128 x 256] @ [256 x 128] =================
    FragC acc[2][4];
#pragma unroll
    for (int mi = 0; mi < 2; mi++)
#pragma unroll
        for (int ni = 0; ni < 4; ni++) wmma::fill_fragment(acc[mi][ni], 0.0f);

    for (int c = 0; c < DIM / KC; c++) {
        const int k0 = c * KC;
        // load X chunk [128 x 64] -> hi/lo bf16 (stride 72)
#pragma unroll
        for (int i = 0; i < 32; i++) {
            int e = t + i * NTHREADS;
            int r = e >> 6, kk = e & 63;
            float v = 0.0f;
            int gr = rowBase + r;
            if (gr < nRows) v = X[(size_t)gr * DIM + k0 + kk];
            __nv_bfloat16 h = __float2bfloat16(v);
            XHI[r * 72 + kk] = h;
            XLO[r * 72 + kk] = __float2bfloat16(v - __bfloat162float(h));
        }
        // load W1 chunk [64 x 128] (stride 136)
#pragma unroll
        for (int i = 0; i < 32; i++) {
            int e = t + i * NTHREADS;
            int r = e >> 7, col = e & 127;
            WHI[r * 136 + col] = g_w1hi[set][(k0 + r) * H1N + col];
            WLO[r * 136 + col] = g_w1lo[set][(k0 + r) * H1N + col];
        }
        __syncthreads();
#pragma unroll
        for (int ks = 0; ks < KC / 16; ks++) {
            const int kb = ks * 16;
            FragA ahi[2], alo[2];
            FragB bhi[4], blo[4];
#pragma unroll
            for (int mi = 0; mi < 2; mi++) {
                wmma::load_matrix_sync(ahi[mi], XHI + (wm * 32 + mi * 16) * 72 + kb, 72);
                wmma::load_matrix_sync(alo[mi], XLO + (wm * 32 + mi * 16) * 72 + kb, 72);
            }
#pragma unroll
            for (int ni = 0; ni < 4; ni++) {
                wmma::load_matrix_sync(bhi[ni], WHI + kb * 136 + wn * 64 + ni * 16, 136);
                wmma::load_matrix_sync(blo[ni], WLO + kb * 136 + wn * 64 + ni * 16, 136);
            }
#pragma unroll
            for (int mi = 0; mi < 2; mi++)
#pragma unroll
                for (int ni = 0; ni < 4; ni++) {
                    wmma::mma_sync(acc[mi][ni], ahi[mi], bhi[ni], acc[mi][ni]);
                    wmma::mma_sync(acc[mi][ni], ahi[mi], blo[ni], acc[mi][ni]);
                    wmma::mma_sync(acc[mi][ni], alo[mi], bhi[ni], acc[mi][ni]);
                }
        }
        __syncthreads();
    }

    // epilogue 1: bias + relu -> split bf16 (stride 136)
#pragma unroll
    for (int mi = 0; mi < 2; mi++)
#pragma unroll
        for (int ni = 0; ni < 4; ni++)
            wmma::store_matrix_sync(H1F + (wm * 32 + mi * 16) * 132 + wn * 64 + ni * 16,
                                    acc[mi][ni], 132, wmma::mem_row_major);
    __syncthreads();
#pragma unroll
    for (int i = 0; i < 64; i++) {
        int e = t + i * NTHREADS;
        int r = e >> 7, col = e & 127;
        float v = H1F[r * 132 + col] + BIAS[col];
        v = fmaxf(v, 0.0f);
        __nv_bfloat16 h = __float2bfloat16(v);
        H1HI[r * 136 + col] = h;
        H1LO[r * 136 + col] = __float2bfloat16(v - __bfloat162float(h));
    }
    // load full W2 [128 x 64] (stride 72)
#pragma unroll
    for (int i = 0; i < 32; i++) {
        int e = t + i * NTHREADS;
        int r = e >> 6, col = e & 63;
        WHI[r * 72 + col] = g_w2hi[set][r * H2N + col];
        WLO[r * 72 + col] = g_w2lo[set][r * H2N + col];
    }
    __syncthreads();

    // ================= GEMM2: [128 x 128] @ [128 x 64] =================
    FragC acc2[2][2];
#pragma unroll
    for (int mi = 0; mi < 2; mi++)
#pragma unroll
        for (int ni = 0; ni < 2; ni++) wmma::fill_fragment(acc2[mi][ni], 0.0f);
#pragma unroll
    for (int ks = 0; ks < H1N / 16; ks++) {
        const int kb = ks * 16;
        FragA ahi[2], alo[2];
        FragB bhi[2], blo[2];
#pragma unroll
        for (int mi = 0; mi < 2; mi++) {
            wmma::load_matrix_sync(ahi[mi], H1HI + (wm * 32 + mi * 16) * 136 + kb, 136);
            wmma::load_matrix_sync(alo[mi], H1LO + (wm * 32 + mi * 16) * 136 + kb, 136);
        }
#pragma unroll
        for (int ni = 0; ni < 2; ni++) {
            wmma::load_matrix_sync(bhi[ni], WHI + kb * 72 + wn * 32 + ni * 16, 72);
            wmma::load_matrix_sync(blo[ni], WLO + kb * 72 + wn * 32 + ni * 16, 72);
        }
#pragma unroll
        for (int mi = 0; mi < 2; mi++)
#pragma unroll
            for (int ni = 0; ni < 2; ni++) {
                wmma::mma_sync(acc2[mi][ni], ahi[mi], bhi[ni], acc2[mi][ni]);
                wmma::mma_sync(acc2[mi][ni], ahi[mi], blo[ni], acc2[mi][ni]);
                wmma::mma_sync(acc2[mi][ni], alo[mi], bhi[ni], acc2[mi][ni]);
            }
    }
#pragma unroll
    for (int mi = 0; mi < 2; mi++)
#pragma unroll
        for (int ni = 0; ni < 2; ni++)
            wmma::store_matrix_sync(H2F + (wm * 32 + mi * 16) * 68 + wn * 32 + ni * 16,
                                    acc2[mi][ni], 68, wmma::mem_row_major);
    __syncthreads();

    // ================= layer 3 + exp + segment sum =================
    if (t < TM) {
        float s = b3g[0];
#pragma unroll
        for (int j = 0; j < H2N; j++) {
            float v = H2F[t * 68 + j] + BIAS[128 + j];
            v = fmaxf(v, 0.0f);
            s = fmaf(v, BIAS[192 + j], s);
        }
        int gr = rowBase + t;
        if (gr < nRows) {
            float e = expf(s);                // max-subtraction omitted: logits are O(1)
            g_ebuf[eOff + gr] = e;
            atomicAdd(&g_segsum[sOff + idx[gr]], e);
        }
    }
}

// ---------------- pool: att-weighted segment sum (sorted indices) ----------------
__global__ void __launch_bounds__(NTHREADS)
pool_kernel(const float* __restrict__ X, const int* __restrict__ idx,
            int eOff, int sOff, float* __restrict__ out, int nRows) {
    __shared__ float rw[POOL_ROWS];
    __shared__ int   sg[POOL_ROWS];
    const int base = blockIdx.x * POOL_ROWS;
    const int rows = min(POOL_ROWS, nRows - base);

    for (int i = threadIdx.x; i < rows; i += NTHREADS) {
        int g = base + i;
        int s = idx[g];
        sg[i] = s;
        rw[i] = g_ebuf[eOff + g] / g_segsum[sOff + s];
    }
    __syncthreads();

    const int col = threadIdx.x;  // 256 threads = 256 columns
    float acc = 0.0f;
    int cur = sg[0];
    float xv = X[(size_t)base * DIM + col];
    for (int i = 0; i < rows; i++) {
        float xn = 0.0f;
        if (i + 1 < rows) xn = X[(size_t)(base + i + 1) * DIM + col];
        int s = sg[i];
        if (s != cur) {
            atomicAdd(&out[(size_t)cur * DIM + col], acc);
            acc = 0.0f;
            cur = s;
        }
        acc = fmaf(rw[i], xv, acc);
        xv = xn;
    }
    atomicAdd(&out[(size_t)cur * DIM + col], acc);
}

// ---------------- launch ----------------
extern "C" void kernel_launch(void* const* d_in, const int* in_sizes, int n_in,
                              void* d_out, int out_size) {
    const float* emb_nodes = (const float*)d_in[0];
    const float* emb_edges = (const float*)d_in[1];
    const int*   node_index = (const int*)d_in[2];
    const int*   edge_index = (const int*)d_in[3];
    const float* Wn1 = (const float*)d_in[4];
    const float* bn1 = (const float*)d_in[5];
    const float* Wn2 = (const float*)d_in[6];
    const float* bn2 = (const float*)d_in[7];
    const float* Wn3 = (const float*)d_in[8];
    const float* bn3 = (const float*)d_in[9];
    const float* We1 = (const float*)d_in[10];
    const float* be1 = (const float*)d_in[11];
    const float* We2 = (const float*)d_in[12];
    const float* be2 = (const float*)d_in[13];
    const float* We3 = (const float*)d_in[14];
    const float* be3 = (const float*)d_in[15];

    const int n_nodes = in_sizes[0] / DIM;   // 200000
    const int n_edges = in_sizes[1] / DIM;   // 400000
    float* out = (float*)d_out;
    const int num_graphs = 2048;
    const int half = num_graphs * DIM;       // 524288

    init_kernel<<<(out_size + NTHREADS - 1) / NTHREADS, NTHREADS>>>(out, out_size);

    const int convN = DIM * H1N + H1N * H2N;  // 40960
    conv_kernel<<<(convN + NTHREADS - 1) / NTHREADS, NTHREADS>>>(Wn1, Wn2, 0);
    conv_kernel<<<(convN + NTHREADS - 1) / NTHREADS, NTHREADS>>>(We1, We2, 1);

    cudaFuncSetAttribute(mlp_kernel, cudaFuncAttributeMaxDynamicSharedMemorySize, SMEM_TOTAL);

    mlp_kernel<<<(n_nodes + TM - 1) / TM, NTHREADS, SMEM_TOTAL>>>(
        emb_nodes, node_index, bn1, bn2, Wn3, bn3, 0, n_nodes, 0, 0);
    mlp_kernel<<<(n_edges + TM - 1) / TM, NTHREADS, SMEM_TOTAL>>>(
        emb_edges, edge_index, be1, be2, We3, be3, 1, n_edges, 200000, 2048);

    pool_kernel<<<(n_nodes + POOL_ROWS - 1) / POOL_ROWS, NTHREADS>>>(
        emb_nodes, node_index, 0, 0, out, n_nodes);
    pool_kernel<<<(n_edges + POOL_ROWS - 1) / POOL_ROWS, NTHREADS>>>(
        emb_edges, edge_index, 200000, 2048, out + half, n_edges);
}

// round 3
// speedup vs baseline: 1.5688x; 1.5677x over previous
#include <cuda_runtime.h>
#include <cuda_bf16.h>
#include <mma.h>
#include <math.h>
#include <stdint.h>

using namespace nvcuda;

// ---------------- problem constants ----------------
#define DIM   256
#define H1N   128
#define H2N   64
#define TM    128      // rows per CTA tile in MLP
#define KC    32       // K-chunk for GEMM1
#define NT    256
#define NGRAPH 2048
#define PROWS 512      // rows per CTA in pool

// ---------------- smem layout (bytes) ----------------
// XB  : 128 x 40 f32 = 20480          (X chunk, tf32-rounded)
// W1B : 32 x 136 f32 = 17408          (W1 chunk)
// W2B : aliases [XB..W1B) : 128 x 72 f32 = 36864 (<= 37888)
// H1  : 128 x 136 f32 = 69632        (H2 128x72 aliases its start)
// BIAS: 256 f32
#define OFF_XB   0
#define OFF_W1B  20480
#define OFF_W2B  0
#define OFF_H1   37888
#define OFF_H2   37888
#define OFF_BIAS 107520
#define SMEM_TOTAL 108608

// ---------------- device scratch ----------------
__device__ float g_w1[2][DIM * H1N];   // tf32-rounded, [k][n]
__device__ float g_w2[2][H1N * H2N];   // tf32-rounded, [k][n]
__device__ float g_ebuf[600064];
__device__ float g_segsum[4096];

static __device__ __forceinline__ float tf32r(float f) {
    uint32_t u;
    asm("cvt.rna.tf32.f32 %0, %1;" : "=r"(u) : "f"(f));
    return __uint_as_float(u);
}

// ---------------- init: zero output + segment sums ----------------
__global__ void init_kernel(float* __restrict__ out, int n) {
    int i = blockIdx.x * blockDim.x + threadIdx.x;
    if (i < n) out[i] = 0.0f;
    if (i < 4096) g_segsum[i] = 0.0f;
}

// ---------------- convert weights -> tf32-rounded f32 (both sets) ----------------
__global__ void conv_kernel(const float* __restrict__ Wn1, const float* __restrict__ Wn2,
                            const float* __restrict__ We1, const float* __restrict__ We2) {
    int i = blockIdx.x * blockDim.x + threadIdx.x;
    const int per = DIM * H1N + H1N * H2N;   // 40960
    if (i >= 2 * per) return;
    int set = i >= per;
    int j = i - set * per;
    const float* W1 = set ? We1 : Wn1;
    const float* W2 = set ? We2 : Wn2;
    if (j < DIM * H1N) g_w1[set][j] = tf32r(W1[j]);
    else               g_w2[set][j - DIM * H1N] = tf32r(W2[j - DIM * H1N]);
}

// ---------------- fused MLP -> exp(logit) + segment sum ----------------
// 256 threads, 8 warps (4x2), 128 rows per CTA. Single-pass TF32 wmma.
__global__ void __launch_bounds__(NT, 2)
mlp_kernel(const float* __restrict__ Xn, const int* __restrict__ idxn,
           const float* __restrict__ bn1, const float* __restrict__ bn2,
           const float* __restrict__ wn3, const float* __restrict__ bn3,
           const float* __restrict__ Xe, const int* __restrict__ idxe,
           const float* __restrict__ be1, const float* __restrict__ be2,
           const float* __restrict__ we3, const float* __restrict__ be3,
           int nTilesNodes, int nNodes, int nEdges) {
    extern __shared__ char smem[];
    float* XB   = (float*)(smem + OFF_XB);
    float* W1B  = (float*)(smem + OFF_W1B);
    float* W2B  = (float*)(smem + OFF_W2B);
    float* H1   = (float*)(smem + OFF_H1);
    float* H2   = (float*)(smem + OFF_H2);
    float* BIAS = (float*)(smem + OFF_BIAS);

    const int bid = blockIdx.x;
    const bool isNode = bid < nTilesNodes;
    const float* X   = isNode ? Xn : Xe;
    const int*   idx = isNode ? idxn : idxe;
    const float* b1  = isNode ? bn1 : be1;
    const float* b2  = isNode ? bn2 : be2;
    const float* w3  = isNode ? wn3 : we3;
    const float* b3  = isNode ? bn3 : be3;
    const int set   = isNode ? 0 : 1;
    const int nRows = isNode ? nNodes : nEdges;
    const int eOff  = isNode ? 0 : 200000;
    const int sOff  = isNode ? 0 : NGRAPH;
    const int rowBase = (isNode ? bid : bid - nTilesNodes) * TM;

    const int t = threadIdx.x;
    const int wid = t >> 5;
    const int wm = wid >> 1;   // 0..3 : 32-row tile
    const int wn = wid & 1;    // 0..1

    if (t < H1N) BIAS[t] = b1[t];
    if (t < H2N) { BIAS[128 + t] = b2[t]; BIAS[192 + t] = w3[t]; }

    typedef wmma::fragment<wmma::matrix_a, 16, 16, 8, wmma::precision::tf32, wmma::row_major> FragA;
    typedef wmma::fragment<wmma::matrix_b, 16, 16, 8, wmma::precision::tf32, wmma::row_major> FragB;
    typedef wmma::fragment<wmma::accumulator, 16, 16, 8, float> FragC;

    // ================= GEMM1: [128 x 256] @ [256 x 128] =================
    FragC acc[2][4];
#pragma unroll
    for (int mi = 0; mi < 2; mi++)
#pragma unroll
        for (int ni = 0; ni < 4; ni++) wmma::fill_fragment(acc[mi][ni], 0.0f);

    for (int c = 0; c < DIM / KC; c++) {
        const int k0 = c * KC;
        // X chunk [128 x 32] -> XB (stride 40), tf32-rounded. 1024 float4 / 256 thr
#pragma unroll
        for (int i = 0; i < 4; i++) {
            int e = t + i * NT;
            int r = e >> 3, kk = (e & 7) * 4;
            int gr = rowBase + r;
            float4 v = make_float4(0.f, 0.f, 0.f, 0.f);
            if (gr < nRows) v = *(const float4*)&X[(size_t)gr * DIM + k0 + kk];
            v.x = tf32r(v.x); v.y = tf32r(v.y); v.z = tf32r(v.z); v.w = tf32r(v.w);
            *(float4*)&XB[r * 40 + kk] = v;
        }
        // W1 chunk [32 x 128] -> W1B (stride 136), pre-rounded in global
#pragma unroll
        for (int i = 0; i < 4; i++) {
            int e = t + i * NT;
            int r = e >> 5, cc = (e & 31) * 4;
            *(float4*)&W1B[r * 136 + cc] = *(const float4*)&g_w1[set][(k0 + r) * H1N + cc];
        }
        __syncthreads();
#pragma unroll
        for (int ks = 0; ks < KC / 8; ks++) {
            const int kb = ks * 8;
            FragA a[2];
            FragB b[4];
#pragma unroll
            for (int mi = 0; mi < 2; mi++)
                wmma::load_matrix_sync(a[mi], XB + (wm * 32 + mi * 16) * 40 + kb, 40);
#pragma unroll
            for (int ni = 0; ni < 4; ni++)
                wmma::load_matrix_sync(b[ni], W1B + kb * 136 + wn * 64 + ni * 16, 136);
#pragma unroll
            for (int mi = 0; mi < 2; mi++)
#pragma unroll
                for (int ni = 0; ni < 4; ni++)
                    wmma::mma_sync(acc[mi][ni], a[mi], b[ni], acc[mi][ni]);
        }
        __syncthreads();
    }

    // epilogue 1: H1 = tf32(relu(acc + b1))
#pragma unroll
    for (int mi = 0; mi < 2; mi++)
#pragma unroll
        for (int ni = 0; ni < 4; ni++)
            wmma::store_matrix_sync(H1 + (wm * 32 + mi * 16) * 136 + wn * 64 + ni * 16,
                                    acc[mi][ni], 136, wmma::mem_row_major);
    __syncthreads();
#pragma unroll
    for (int i = 0; i < 16; i++) {
        int e = t + i * NT;
        int r = e >> 5, cc = (e & 31) * 4;
        float4 v = *(float4*)&H1[r * 136 + cc];
        v.x = tf32r(fmaxf(v.x + BIAS[cc + 0], 0.f));
        v.y = tf32r(fmaxf(v.y + BIAS[cc + 1], 0.f));
        v.z = tf32r(fmaxf(v.z + BIAS[cc + 2], 0.f));
        v.w = tf32r(fmaxf(v.w + BIAS[cc + 3], 0.f));
        *(float4*)&H1[r * 136 + cc] = v;
    }
    // W2 [128 x 64] -> W2B (stride 72), aliases XB/W1B (done with them)
#pragma unroll
    for (int i = 0; i < 8; i++) {
        int e = t + i * NT;
        int r = e >> 4, cc = (e & 15) * 4;
        *(float4*)&W2B[r * 72 + cc] = *(const float4*)&g_w2[set][r * H2N + cc];
    }
    __syncthreads();

    // ================= GEMM2: [128 x 128] @ [128 x 64] =================
    FragC acc2[2][2];
#pragma unroll
    for (int mi = 0; mi < 2; mi++)
#pragma unroll
        for (int ni = 0; ni < 2; ni++) wmma::fill_fragment(acc2[mi][ni], 0.0f);
#pragma unroll
    for (int ks = 0; ks < H1N / 8; ks++) {
        const int kb = ks * 8;
        FragA a[2];
        FragB b[2];
#pragma unroll
        for (int mi = 0; mi < 2; mi++)
            wmma::load_matrix_sync(a[mi], H1 + (wm * 32 + mi * 16) * 136 + kb, 136);
#pragma unroll
        for (int ni = 0; ni < 2; ni++)
            wmma::load_matrix_sync(b[ni], W2B + kb * 72 + wn * 32 + ni * 16, 72);
#pragma unroll
        for (int mi = 0; mi < 2; mi++)
#pragma unroll
            for (int ni = 0; ni < 2; ni++)
                wmma::mma_sync(acc2[mi][ni], a[mi], b[ni], acc2[mi][ni]);
    }
    __syncthreads();   // all H1 reads done before overwriting with H2
#pragma unroll
    for (int mi = 0; mi < 2; mi++)
#pragma unroll
        for (int ni = 0; ni < 2; ni++)
            wmma::store_matrix_sync(H2 + (wm * 32 + mi * 16) * 72 + wn * 32 + ni * 16,
                                    acc2[mi][ni], 72, wmma::mem_row_major);
    __syncthreads();

    // ================= layer 3 + exp + segment sum =================
    if (t < TM) {
        int gr = rowBase + t;
        if (gr < nRows) {
            float s = b3[0];
#pragma unroll
            for (int j = 0; j < H2N; j++) {
                float v = fmaxf(H2[t * 72 + j] + BIAS[128 + j], 0.0f);
                s = fmaf(v, BIAS[192 + j], s);
            }
            float e = expf(s);   // logits O(1): max-subtraction unnecessary
            g_ebuf[eOff + gr] = e;
            atomicAdd(&g_segsum[sOff + idx[gr]], e);
        }
    }
}

// ---------------- pool: att-weighted segment sum (sorted indices) ----------------
// 512 rows/CTA, 4 groups x 64 threads, float4 columns.
__global__ void __launch_bounds__(NT)
pool_kernel(const float* __restrict__ Xn, const int* __restrict__ idxn,
            const float* __restrict__ Xe, const int* __restrict__ idxe,
            float* __restrict__ out, int nbNodes, int nNodes, int nEdges) {
    __shared__ float rw[PROWS];
    __shared__ int   sg[PROWS];

    const int bid = blockIdx.x;
    const bool isNode = bid < nbNodes;
    const float* X   = isNode ? Xn : Xe;
    const int*   idx = isNode ? idxn : idxe;
    const int nRows  = isNode ? nNodes : nEdges;
    const int eOff   = isNode ? 0 : 200000;
    const int sOff   = isNode ? 0 : NGRAPH;
    float* outH      = isNode ? out : out + NGRAPH * DIM;
    const int base   = (isNode ? bid : bid - nbNodes) * PROWS;
    const int rows   = min(PROWS, nRows - base);

    const int t = threadIdx.x;
    for (int i = t; i < rows; i += NT) {
        int g = base + i;
        int s = idx[g];
        sg[i] = s;
        rw[i] = g_ebuf[eOff + g] / g_segsum[sOff + s];
    }
    __syncthreads();

    const int grp = t >> 6;          // 0..3
    const int col = (t & 63) * 4;    // float4 column
    const int r0 = grp * 128;
    if (r0 < rows) {
        const int rend = min(r0 + 128, rows);
        float4 acc = make_float4(0.f, 0.f, 0.f, 0.f);
        int cur = sg[r0];
        for (int i = r0; i < rend; i++) {
            float4 x = *(const float4*)&X[(size_t)(base + i) * DIM + col];
            int s = sg[i];
            if (s != cur) {
                size_t o = (size_t)cur * DIM + col;
                atomicAdd(&outH[o + 0], acc.x);
                atomicAdd(&outH[o + 1], acc.y);
                atomicAdd(&outH[o + 2], acc.z);
                atomicAdd(&outH[o + 3], acc.w);
                acc = make_float4(0.f, 0.f, 0.f, 0.f);
                cur = s;
            }
            float w = rw[i];
            acc.x = fmaf(w, x.x, acc.x);
            acc.y = fmaf(w, x.y, acc.y);
            acc.z = fmaf(w, x.z, acc.z);
            acc.w = fmaf(w, x.w, acc.w);
        }
        size_t o = (size_t)cur * DIM + col;
        atomicAdd(&outH[o + 0], acc.x);
        atomicAdd(&outH[o + 1], acc.y);
        atomicAdd(&outH[o + 2], acc.z);
        atomicAdd(&outH[o + 3], acc.w);
    }
}

// ---------------- launch ----------------
extern "C" void kernel_launch(void* const* d_in, const int* in_sizes, int n_in,
                              void* d_out, int out_size) {
    const float* emb_nodes  = (const float*)d_in[0];
    const float* emb_edges  = (const float*)d_in[1];
    const int*   node_index = (const int*)d_in[2];
    const int*   edge_index = (const int*)d_in[3];
    const float* Wn1 = (const float*)d_in[4];
    const float* bn1 = (const float*)d_in[5];
    const float* Wn2 = (const float*)d_in[6];
    const float* bn2 = (const float*)d_in[7];
    const float* Wn3 = (const float*)d_in[8];
    const float* bn3 = (const float*)d_in[9];
    const float* We1 = (const float*)d_in[10];
    const float* be1 = (const float*)d_in[11];
    const float* We2 = (const float*)d_in[12];
    const float* be2 = (const float*)d_in[13];
    const float* We3 = (const float*)d_in[14];
    const float* be3 = (const float*)d_in[15];

    const int n_nodes = in_sizes[0] / DIM;   // 200000
    const int n_edges = in_sizes[1] / DIM;   // 400000
    float* out = (float*)d_out;

    init_kernel<<<(out_size + NT - 1) / NT, NT>>>(out, out_size);

    const int convN = 2 * (DIM * H1N + H1N * H2N);
    conv_kernel<<<(convN + NT - 1) / NT, NT>>>(Wn1, Wn2, We1, We2);

    cudaFuncSetAttribute(mlp_kernel, cudaFuncAttributeMaxDynamicSharedMemorySize, SMEM_TOTAL);

    const int tn = (n_nodes + TM - 1) / TM;
    const int te = (n_edges + TM - 1) / TM;
    mlp_kernel<<<tn + te, NT, SMEM_TOTAL>>>(
        emb_nodes, node_index, bn1, bn2, Wn3, bn3,
        emb_edges, edge_index, be1, be2, We3, be3,
        tn, n_nodes, n_edges);

    const int pn = (n_nodes + PROWS - 1) / PROWS;
    const int pe = (n_edges + PROWS - 1) / PROWS;
    pool_kernel<<<pn + pe, NT>>>(
        emb_nodes, node_index, emb_edges, edge_index, out, pn, n_nodes, n_edges);
}

// round 6
// speedup vs baseline: 1.7617x; 1.1230x over previous
#include <cuda_runtime.h>
#include <cuda_bf16.h>
#include <mma.h>
#include <math.h>
#include <stdint.h>

using namespace nvcuda;

// ---------------- problem constants ----------------
#define DIM   256
#define H1N   128
#define H2N   64
#define TM    128      // rows per CTA tile
#define KC    32       // K-chunk for GEMM1
#define NT    256
#define NGRAPH 2048
#define PROWS 512

// ---------------- smem layout (float offsets via bytes) ----------------
// XB0/XB1 : 128 x 36 f32 = 18432 B each           (X chunk double buffer)
// W1B0/W1B1: 32 x 132 f32 = 16896 B each          (W1 chunk double buffer)
// H1      : 128 x 132 f32 = 67584 B  (aliases XB0..W1B1 region, 70656 B)
// W2B     : 128 x 68 f32 = 34816 B   (H2 aliases it: 128 x 68)
// BIAS    : 256 f32
#define OFF_XB0  0
#define OFF_XB1  18432
#define OFF_W1B0 36864
#define OFF_W1B1 53760
#define OFF_H1   0
#define OFF_W2   70656
#define OFF_H2   70656
#define OFF_BIAS 105472
#define SMEM_TOTAL 106496

// ---------------- device scratch ----------------
__device__ float g_ebuf[600064];
__device__ float g_segsum[4096];

// ---------------- cp.async helpers ----------------
static __device__ __forceinline__ uint32_t s2u(const void* p) {
    uint32_t a;
    asm("{ .reg .u64 t; cvta.to.shared.u64 t, %1; cvt.u32.u64 %0, t; }" : "=r"(a) : "l"(p));
    return a;
}
#define CP16(dst, src) \
    asm volatile("cp.async.cg.shared.global [%0], [%1], 16;" :: "r"(dst), "l"(src))
#define CP_COMMIT() asm volatile("cp.async.commit_group;" ::: "memory")
#define CP_WAIT(n)  asm volatile("cp.async.wait_group %0;" :: "n"(n) : "memory")

// ---------------- init: zero output + segment sums ----------------
__global__ void init_kernel(float* __restrict__ out, int n) {
    int i = blockIdx.x * blockDim.x + threadIdx.x;
    if (i < n) out[i] = 0.0f;
    if (i < 4096) g_segsum[i] = 0.0f;
}

// ---------------- fused MLP: cp.async double-buffered tf32 wmma ----------------
// 256 threads, 8 warps (4 row-tiles x 2 col-tiles), 128 rows/CTA, 2 CTAs/SM.
__global__ void __launch_bounds__(NT, 2)
mlp_kernel(const float* __restrict__ Xn, const int* __restrict__ idxn,
           const float* __restrict__ Wn1, const float* __restrict__ bn1,
           const float* __restrict__ Wn2, const float* __restrict__ bn2,
           const float* __restrict__ wn3, const float* __restrict__ bn3,
           const float* __restrict__ Xe, const int* __restrict__ idxe,
           const float* __restrict__ We1, const float* __restrict__ be1,
           const float* __restrict__ We2, const float* __restrict__ be2,
           const float* __restrict__ we3, const float* __restrict__ be3,
           int nTilesNodes, int nNodes, int nEdges) {
    extern __shared__ char smem[];
    float* H1   = (float*)(smem + OFF_H1);
    float* W2B  = (float*)(smem + OFF_W2);
    float* H2   = (float*)(smem + OFF_H2);
    float* BIAS = (float*)(smem + OFF_BIAS);
    const uint32_t sb = s2u(smem);

    const int bid = blockIdx.x;
    const bool isNode = bid < nTilesNodes;
    const float* X   = isNode ? Xn : Xe;
    const int*   idx = isNode ? idxn : idxe;
    const float* W1  = isNode ? Wn1 : We1;
    const float* W2  = isNode ? Wn2 : We2;
    const float* b1  = isNode ? bn1 : be1;
    const float* b2  = isNode ? bn2 : be2;
    const float* w3  = isNode ? wn3 : we3;
    const float* b3  = isNode ? bn3 : be3;
    const int nRows  = isNode ? nNodes : nEdges;
    const int eOff   = isNode ? 0 : 200000;
    const int sOff   = isNode ? 0 : NGRAPH;
    const int rowBase = (isNode ? bid : bid - nTilesNodes) * TM;

    const int t = threadIdx.x;
    const int wid = t >> 5;
    const int wm = wid >> 1;   // 0..3
    const int wn = wid & 1;    // 0..1

    if (t < H1N) BIAS[t] = b1[t];
    if (t < H2N) { BIAS[128 + t] = b2[t]; BIAS[192 + t] = w3[t]; }

    // ---- thread's fixed load slots ----
    // X chunk: 1024 float4 -> r = e>>3, kk = (e&7)*4
    const int xr = t >> 1;               // with i-loop below
    // W1 chunk: 1024 float4 -> r = e>>5, cc = (e&31)*4

    // ---- prefetch chunk 0 + W2 (group 0) ----
    {
        // X chunk 0
#pragma unroll
        for (int i = 0; i < 4; i++) {
            int e = t + i * NT;
            int r = e >> 3, kk = (e & 7) * 4;
            int gr = rowBase + r; if (gr >= nRows) gr = nRows - 1;
            CP16(sb + OFF_XB0 + (r * 36 + kk) * 4, &X[(size_t)gr * DIM + kk]);
        }
        // W1 chunk 0
#pragma unroll
        for (int i = 0; i < 4; i++) {
            int e = t + i * NT;
            int r = e >> 5, cc = (e & 31) * 4;
            CP16(sb + OFF_W1B0 + (r * 132 + cc) * 4, &W1[r * H1N + cc]);
        }
        // W2 full [128 x 64]
#pragma unroll
        for (int i = 0; i < 8; i++) {
            int e = t + i * NT;
            int r = e >> 4, cc = (e & 15) * 4;
            CP16(sb + OFF_W2 + (r * 68 + cc) * 4, &W2[r * H2N + cc]);
        }
        CP_COMMIT();
    }

    typedef wmma::fragment<wmma::matrix_a, 16, 16, 8, wmma::precision::tf32, wmma::row_major> FragA;
    typedef wmma::fragment<wmma::matrix_b, 16, 16, 8, wmma::precision::tf32, wmma::row_major> FragB;
    typedef wmma::fragment<wmma::accumulator, 16, 16, 8, float> FragC;

    // ================= GEMM1: [128 x 256] @ [256 x 128] =================
    FragC acc[2][4];
#pragma unroll
    for (int mi = 0; mi < 2; mi++)
#pragma unroll
        for (int ni = 0; ni < 4; ni++) wmma::fill_fragment(acc[mi][ni], 0.0f);

    const int NCHUNK = DIM / KC;  // 8
    for (int c = 0; c < NCHUNK; c++) {
        // prefetch chunk c+1 into other buffer
        if (c + 1 < NCHUNK) {
            const int k0 = (c + 1) * KC;
            const uint32_t xb = (c + 1) & 1 ? OFF_XB1 : OFF_XB0;
            const uint32_t wb = (c + 1) & 1 ? OFF_W1B1 : OFF_W1B0;
#pragma unroll
            for (int i = 0; i < 4; i++) {
                int e = t + i * NT;
                int r = e >> 3, kk = (e & 7) * 4;
                int gr = rowBase + r; if (gr >= nRows) gr = nRows - 1;
                CP16(sb + xb + (r * 36 + kk) * 4, &X[(size_t)gr * DIM + k0 + kk]);
            }
#pragma unroll
            for (int i = 0; i < 4; i++) {
                int e = t + i * NT;
                int r = e >> 5, cc = (e & 31) * 4;
                CP16(sb + wb + (r * 132 + cc) * 4, &W1[(k0 + r) * H1N + cc]);
            }
            CP_COMMIT();
            CP_WAIT(1);    // chunk c resident
        } else {
            CP_WAIT(0);    // final chunk (and everything) resident
        }
        __syncthreads();

        float* XB  = (float*)(smem + ((c & 1) ? OFF_XB1 : OFF_XB0));
        float* W1B = (float*)(smem + ((c & 1) ? OFF_W1B1 : OFF_W1B0));
#pragma unroll
        for (int ks = 0; ks < KC / 8; ks++) {
            const int kb = ks * 8;
            FragA a[2];
            FragB b[4];
#pragma unroll
            for (int mi = 0; mi < 2; mi++)
                wmma::load_matrix_sync(a[mi], XB + (wm * 32 + mi * 16) * 36 + kb, 36);
#pragma unroll
            for (int ni = 0; ni < 4; ni++)
                wmma::load_matrix_sync(b[ni], W1B + kb * 132 + wn * 64 + ni * 16, 132);
#pragma unroll
            for (int mi = 0; mi < 2; mi++)
#pragma unroll
                for (int ni = 0; ni < 4; ni++)
                    wmma::mma_sync(acc[mi][ni], a[mi], b[ni], acc[mi][ni]);
        }
        __syncthreads();   // buffer (c&1) free for prefetch of chunk c+2
    }

    // ---- epilogue 1: H1 = relu(acc + b1)  (H1 aliases X/W1 buffers) ----
#pragma unroll
    for (int mi = 0; mi < 2; mi++)
#pragma unroll
        for (int ni = 0; ni < 4; ni++)
            wmma::store_matrix_sync(H1 + (wm * 32 + mi * 16) * 132 + wn * 64 + ni * 16,
                                    acc[mi][ni], 132, wmma::mem_row_major);
    __syncthreads();
#pragma unroll
    for (int i = 0; i < 16; i++) {
        int e = t + i * NT;
        int r = e >> 5, cc = (e & 31) * 4;
        float4 v = *(float4*)&H1[r * 132 + cc];
        v.x = fmaxf(v.x + BIAS[cc + 0], 0.f);
        v.y = fmaxf(v.y + BIAS[cc + 1], 0.f);
        v.z = fmaxf(v.z + BIAS[cc + 2], 0.f);
        v.w = fmaxf(v.w + BIAS[cc + 3], 0.f);
        *(float4*)&H1[r * 132 + cc] = v;
    }
    __syncthreads();

    // ================= GEMM2: [128 x 128] @ [128 x 64] =================
    FragC acc2[2][2];
#pragma unroll
    for (int mi = 0; mi < 2; mi++)
#pragma unroll
        for (int ni = 0; ni < 2; ni++) wmma::fill_fragment(acc2[mi][ni], 0.0f);
#pragma unroll
    for (int ks = 0; ks < H1N / 8; ks++) {
        const int kb = ks * 8;
        FragA a[2];
        FragB b[2];
#pragma unroll
        for (int mi = 0; mi < 2; mi++)
            wmma::load_matrix_sync(a[mi], H1 + (wm * 32 + mi * 16) * 132 + kb, 132);
#pragma unroll
        for (int ni = 0; ni < 2; ni++)
            wmma::load_matrix_sync(b[ni], W2B + kb * 68 + wn * 32 + ni * 16, 68);
#pragma unroll
        for (int mi = 0; mi < 2; mi++)
#pragma unroll
            for (int ni = 0; ni < 2; ni++)
                wmma::mma_sync(acc2[mi][ni], a[mi], b[ni], acc2[mi][ni]);
    }
    __syncthreads();   // W2B reads done before H2 overwrites it
#pragma unroll
    for (int mi = 0; mi < 2; mi++)
#pragma unroll
        for (int ni = 0; ni < 2; ni++)
            wmma::store_matrix_sync(H2 + (wm * 32 + mi * 16) * 68 + wn * 32 + ni * 16,
                                    acc2[mi][ni], 68, wmma::mem_row_major);
    __syncthreads();

    // ================= layer 3 + exp + segment sum =================
    if (t < TM) {
        int gr = rowBase + t;
        if (gr < nRows) {
            float s = b3[0];
#pragma unroll
            for (int j = 0; j < H2N; j++) {
                float v = fmaxf(H2[t * 68 + j] + BIAS[128 + j], 0.0f);
                s = fmaf(v, BIAS[192 + j], s);
            }
            float e = expf(s);   // logits O(1): no max-subtraction needed
            g_ebuf[eOff + gr] = e;
            atomicAdd(&g_segsum[sOff + idx[gr]], e);
        }
    }
}

// ---------------- pool: att-weighted segment sum (sorted indices) ----------------
__global__ void __launch_bounds__(NT)
pool_kernel(const float* __restrict__ Xn, const int* __restrict__ idxn,
            const float* __restrict__ Xe, const int* __restrict__ idxe,
            float* __restrict__ out, int nbNodes, int nNodes, int nEdges) {
    __shared__ float rw[PROWS];
    __shared__ int   sg[PROWS];

    const int bid = blockIdx.x;
    const bool isNode = bid < nbNodes;
    const float* X   = isNode ? Xn : Xe;
    const int*   idx = isNode ? idxn : idxe;
    const int nRows  = isNode ? nNodes : nEdges;
    const int eOff   = isNode ? 0 : 200000;
    const int sOff   = isNode ? 0 : NGRAPH;
    float* outH      = isNode ? out : out + NGRAPH * DIM;
    const int base   = (isNode ? bid : bid - nbNodes) * PROWS;
    const int rows   = min(PROWS, nRows - base);

    const int t = threadIdx.x;
    for (int i = t; i < rows; i += NT) {
        int g = base + i;
        int s = idx[g];
        sg[i] = s;
        rw[i] = g_ebuf[eOff + g] / g_segsum[sOff + s];
    }
    __syncthreads();

    const int grp = t >> 6;
    const int col = (t & 63) * 4;
    const int r0 = grp * 128;
    if (r0 < rows) {
        const int rend = min(r0 + 128, rows);
        float4 acc = make_float4(0.f, 0.f, 0.f, 0.f);
        int cur = sg[r0];
        for (int i = r0; i < rend; i++) {
            float4 x = *(const float4*)&X[(size_t)(base + i) * DIM + col];
            int s = sg[i];
            if (s != cur) {
                size_t o = (size_t)cur * DIM + col;
                atomicAdd(&outH[o + 0], acc.x);
                atomicAdd(&outH[o + 1], acc.y);
                atomicAdd(&outH[o + 2], acc.z);
                atomicAdd(&outH[o + 3], acc.w);
                acc = make_float4(0.f, 0.f, 0.f, 0.f);
                cur = s;
            }
            float w = rw[i];
            acc.x = fmaf(w, x.x, acc.x);
            acc.y = fmaf(w, x.y, acc.y);
            acc.z = fmaf(w, x.z, acc.z);
            acc.w = fmaf(w, x.w, acc.w);
        }
        size_t o = (size_t)cur * DIM + col;
        atomicAdd(&outH[o + 0], acc.x);
        atomicAdd(&outH[o + 1], acc.y);
        atomicAdd(&outH[o + 2], acc.z);
        atomicAdd(&outH[o + 3], acc.w);
    }
}

// ---------------- launch ----------------
extern "C" void kernel_launch(void* const* d_in, const int* in_sizes, int n_in,
                              void* d_out, int out_size) {
    const float* emb_nodes  = (const float*)d_in[0];
    const float* emb_edges  = (const float*)d_in[1];
    const int*   node_index = (const int*)d_in[2];
    const int*   edge_index = (const int*)d_in[3];
    const float* Wn1 = (const float*)d_in[4];
    const float* bn1 = (const float*)d_in[5];
    const float* Wn2 = (const float*)d_in[6];
    const float* bn2 = (const float*)d_in[7];
    const float* Wn3 = (const float*)d_in[8];
    const float* bn3 = (const float*)d_in[9];
    const float* We1 = (const float*)d_in[10];
    const float* be1 = (const float*)d_in[11];
    const float* We2 = (const float*)d_in[12];
    const float* be2 = (const float*)d_in[13];
    const float* We3 = (const float*)d_in[14];
    const float* be3 = (const float*)d_in[15];

    const int n_nodes = in_sizes[0] / DIM;   // 200000
    const int n_edges = in_sizes[1] / DIM;   // 400000
    float* out = (float*)d_out;

    init_kernel<<<(out_size + NT - 1) / NT, NT>>>(out, out_size);

    cudaFuncSetAttribute(mlp_kernel, cudaFuncAttributeMaxDynamicSharedMemorySize, SMEM_TOTAL);

    const int tn = (n_nodes + TM - 1) / TM;
    const int te = (n_edges + TM - 1) / TM;
    mlp_kernel<<<tn + te, NT, SMEM_TOTAL>>>(
        emb_nodes, node_index, Wn1, bn1, Wn2, bn2, Wn3, bn3,
        emb_edges, edge_index, We1, be1, We2, be2, We3, be3,
        tn, n_nodes, n_edges);

    const int pn = (n_nodes + PROWS - 1) / PROWS;
    const int pe = (n_edges + PROWS - 1) / PROWS;
    pool_kernel<<<pn + pe, NT>>>(
        emb_nodes, node_index, emb_edges, edge_index, out, pn, n_nodes, n_edges);
}